// round 6
// baseline (speedup 1.0000x reference)
#include <cuda_runtime.h>

#define MAXN     102400
#define IN_FEATS 16
#define UNROLL   4

// Scratch (device globals — no allocation allowed)
__device__ int    g_deg[MAXN];
__device__ float  g_norm[MAXN];
__device__ float4 g_Us[MAXN];    // norm-prescaled X0·[M1|M2]
__device__ float2 g_XA[MAXN];    // X0·M0
__device__ float4 g_Vacc[MAXN];  // pass-1 accumulator (xy: M1 part, zw: M2 part)
__device__ float2 g_Zs[MAXN];    // norm²-scaled M2-half of pass-1 result
__device__ float2 g_Tacc[MAXN];  // pass-2 accumulator
__device__ float  g_M0[32], g_M1[32], g_M2[32];  // [j*2+o]
__device__ int    g_is64;

// --- init: zero accumulators, fold weights, detect index width ---
__global__ void k_init(const float* __restrict__ W,
                       const float* __restrict__ lam,
                       const unsigned* __restrict__ srcw, int E, int N) {
    int i = blockIdx.x * blockDim.x + threadIdx.x;
    if (i < N) {
        g_deg[i]  = 0;
        g_Vacc[i] = make_float4(0.f, 0.f, 0.f, 0.f);
        g_Tacc[i] = make_float2(0.f, 0.f);
    }
    if (blockIdx.x == 0) {
        if (threadIdx.x < 32) {
            int j = threadIdx.x >> 1, o = threadIdx.x & 1;
            float r = 2.0f / __ldg(lam);
            float A = __ldg(W + o * 48 + j);
            float B = __ldg(W + o * 48 + 16 + j);
            float C = __ldg(W + o * 48 + 32 + j);
            float rm1 = r - 1.0f;
            g_M0[threadIdx.x] = A + rm1 * B + (2.0f * rm1 * rm1 - 1.0f) * C;
            g_M1[threadIdx.x] = -r * B - 4.0f * r * rm1 * C;
            g_M2[threadIdx.x] = 2.0f * r * r * C;
        }
        // int64-vs-int32 detection: high words of valid int64 indices are 0
        __shared__ int s_any;
        if (threadIdx.x == 0) s_any = 0;
        __syncthreads();
        int limit = (E < 4096) ? E : 4096;
        for (int k = threadIdx.x; k < limit; k += blockDim.x)
            if (srcw[2 * k + 1] != 0u) s_any = 1;
        __syncthreads();
        if (threadIdx.x == 0) g_is64 = (s_any == 0) ? 1 : 0;
    }
}

__device__ __forceinline__ int ld_idx(const void* p, int e, int is64) {
    return is64 ? (int)__ldcs((const long long*)p + e)
                : __ldcs((const int*)p + e);
}

// --- degree-only pass: one int red per edge, reads dst stream only ---
__global__ void k_deg(const void* __restrict__ dstv, int E) {
    int tid = blockIdx.x * blockDim.x + threadIdx.x;
    int S = gridDim.x * blockDim.x;
    int is64 = g_is64;
    int d[UNROLL]; bool v[UNROLL];
#pragma unroll
    for (int j = 0; j < UNROLL; j++) {
        int e = tid + j * S;
        v[j] = (e < E);
        d[j] = ld_idx(dstv, v[j] ? e : 0, is64);
    }
#pragma unroll
    for (int j = 0; j < UNROLL; j++)
        if (v[j]) atomicAdd(&g_deg[d[j]], 1);
}

// --- per-node: norm + projections (weights staged in shared) ---
__global__ void k_node(const float* __restrict__ x, int N) {
    __shared__ float sM0[32], sM1[32], sM2[32];
    if (threadIdx.x < 32) {
        sM0[threadIdx.x] = g_M0[threadIdx.x];
        sM1[threadIdx.x] = g_M1[threadIdx.x];
        sM2[threadIdx.x] = g_M2[threadIdx.x];
    }
    __syncthreads();
    int i = blockIdx.x * blockDim.x + threadIdx.x;
    if (i >= N) return;
    float nrm = rsqrtf((float)max(g_deg[i], 1));
    g_norm[i] = nrm;
    float u0 = 0.f, u1 = 0.f, u2 = 0.f, u3 = 0.f, a0 = 0.f, a1 = 0.f;
    const float4* xr = (const float4*)(x + (size_t)i * IN_FEATS);
#pragma unroll
    for (int q = 0; q < 4; q++) {
        float4 xv = __ldg(xr + q);
        float vals[4] = {xv.x, xv.y, xv.z, xv.w};
#pragma unroll
        for (int t = 0; t < 4; t++) {
            int j = q * 4 + t;
            float xj = vals[t];
            a0 += xj * sM0[2 * j];  a1 += xj * sM0[2 * j + 1];
            u0 += xj * sM1[2 * j];  u1 += xj * sM1[2 * j + 1];
            u2 += xj * sM2[2 * j];  u3 += xj * sM2[2 * j + 1];
        }
    }
    g_Us[i] = make_float4(u0 * nrm, u1 * nrm, u2 * nrm, u3 * nrm);
    g_XA[i] = make_float2(a0, a1);
}

// --- propagation pass 1: Vacc[dst] += Us[src] (direct int64 edge reads) ---
__global__ void k_prop1(const void* __restrict__ srcv,
                        const void* __restrict__ dstv, int E) {
    int tid = blockIdx.x * blockDim.x + threadIdx.x;
    int S = gridDim.x * blockDim.x;
    int is64 = g_is64;
    int s[UNROLL], d[UNROLL]; bool v[UNROLL];
    float4 u[UNROLL];
#pragma unroll
    for (int j = 0; j < UNROLL; j++) {
        int e = tid + j * S;
        v[j] = (e < E);
        int ee = v[j] ? e : 0;
        s[j] = ld_idx(srcv, ee, is64);
        d[j] = ld_idx(dstv, ee, is64);
    }
#pragma unroll
    for (int j = 0; j < UNROLL; j++)
        u[j] = __ldg(&g_Us[s[j]]);
#pragma unroll
    for (int j = 0; j < UNROLL; j++)
        if (v[j]) atomicAdd(&g_Vacc[d[j]], u[j]);
}

// --- finalize pass 1: Zs = norm²·(M2 part) only ---
__global__ void k_fin1(int N) {
    int i = blockIdx.x * blockDim.x + threadIdx.x;
    if (i >= N) return;
    float nrm = g_norm[i];
    float4 vv = g_Vacc[i];
    float n2 = nrm * nrm;
    g_Zs[i] = make_float2(vv.z * n2, vv.w * n2);
}

// --- propagation pass 2: Tacc[dst] += Zs[src] ---
__global__ void k_prop2(const void* __restrict__ srcv,
                        const void* __restrict__ dstv, int E) {
    int tid = blockIdx.x * blockDim.x + threadIdx.x;
    int S = gridDim.x * blockDim.x;
    int is64 = g_is64;
    int s[UNROLL], d[UNROLL]; bool v[UNROLL];
    float2 z[UNROLL];
#pragma unroll
    for (int j = 0; j < UNROLL; j++) {
        int e = tid + j * S;
        v[j] = (e < E);
        int ee = v[j] ? e : 0;
        s[j] = ld_idx(srcv, ee, is64);
        d[j] = ld_idx(dstv, ee, is64);
    }
#pragma unroll
    for (int j = 0; j < UNROLL; j++)
        z[j] = __ldg(&g_Zs[s[j]]);
#pragma unroll
    for (int j = 0; j < UNROLL; j++)
        if (v[j]) atomicAdd(&g_Tacc[d[j]], z[j]);
}

// --- epilogue: h = relu(XA + nrm·Vacc.xy + nrm·Tacc) ---
__global__ void k_out(float2* __restrict__ out, int N) {
    int i = blockIdx.x * blockDim.x + threadIdx.x;
    if (i >= N) return;
    float nrm = g_norm[i];
    float4 vv = g_Vacc[i];
    float2 t = g_Tacc[i], a = g_XA[i];
    out[i] = make_float2(fmaxf(a.x + (vv.x + t.x) * nrm, 0.0f),
                         fmaxf(a.y + (vv.y + t.y) * nrm, 0.0f));
}

extern "C" void kernel_launch(void* const* d_in, const int* in_sizes, int n_in,
                              void* d_out, int out_size) {
    const float* in_feat = (const float*)d_in[0];
    const float* W       = (const float*)d_in[1];
    const void*  src     = d_in[2];
    const void*  dst     = d_in[3];
    const float* lam     = (const float*)d_in[4];

    int N = in_sizes[0] / IN_FEATS;
    int E = in_sizes[2];
    const int TB = 256;
    int nb  = (N + TB - 1) / TB;
    int eb4 = (E + TB * UNROLL - 1) / (TB * UNROLL);

    k_init<<<nb, TB>>>(W, lam, (const unsigned*)src, E, N);
    k_deg<<<eb4, TB>>>(dst, E);
    k_node<<<nb, TB>>>(in_feat, N);
    k_prop1<<<eb4, TB>>>(src, dst, E);
    k_fin1<<<nb, TB>>>(N);
    k_prop2<<<eb4, TB>>>(src, dst, E);
    k_out<<<nb, TB>>>((float2*)d_out, N);
}

// round 7
// speedup vs baseline: 1.0026x; 1.0026x over previous
#include <cuda_runtime.h>

#define MAXN     102400
#define IN_FEATS 16
#define UNROLL   4

// Scratch (device globals — no allocation allowed)
__device__ int    g_deg[MAXN];
__device__ float  g_norm[MAXN];
__device__ float4 g_Us[MAXN];    // norm-prescaled X0·[M1|M2]
__device__ float2 g_XA[MAXN];    // X0·M0
__device__ float4 g_Vacc[MAXN];  // pass-1 accumulator (xy: M1 part, zw: M2 part)
__device__ float2 g_Zs[MAXN];    // norm²-scaled M2-half of pass-1 result
__device__ float2 g_Tacc[MAXN];  // pass-2 accumulator
__device__ float  g_M0[32], g_M1[32], g_M2[32];  // [j*2+o]
__device__ int    g_is64;

// --- init: zero accumulators, fold weights, detect index width ---
__global__ void k_init(const float* __restrict__ W,
                       const float* __restrict__ lam,
                       const unsigned* __restrict__ srcw, int E, int N) {
    int i = blockIdx.x * blockDim.x + threadIdx.x;
    if (i < N) {
        g_deg[i]  = 0;
        g_Vacc[i] = make_float4(0.f, 0.f, 0.f, 0.f);
        g_Tacc[i] = make_float2(0.f, 0.f);
    }
    if (blockIdx.x == 0) {
        if (threadIdx.x < 32) {
            int j = threadIdx.x >> 1, o = threadIdx.x & 1;
            float r = 2.0f / __ldg(lam);
            float A = __ldg(W + o * 48 + j);
            float B = __ldg(W + o * 48 + 16 + j);
            float C = __ldg(W + o * 48 + 32 + j);
            float rm1 = r - 1.0f;
            g_M0[threadIdx.x] = A + rm1 * B + (2.0f * rm1 * rm1 - 1.0f) * C;
            g_M1[threadIdx.x] = -r * B - 4.0f * r * rm1 * C;
            g_M2[threadIdx.x] = 2.0f * r * r * C;
        }
        __shared__ int s_any;
        if (threadIdx.x == 0) s_any = 0;
        __syncthreads();
        int limit = (E < 4096) ? E : 4096;
        for (int k = threadIdx.x; k < limit; k += blockDim.x)
            if (srcw[2 * k + 1] != 0u) s_any = 1;
        __syncthreads();
        if (threadIdx.x == 0) g_is64 = (s_any == 0) ? 1 : 0;
    }
}

// --- degree pass: vectorized dst reads, 4 edges/thread ---
__global__ void k_deg(const void* __restrict__ dstv, int E) {
    int tid = blockIdx.x * blockDim.x + threadIdx.x;
    int S = gridDim.x * blockDim.x;
    int P = E >> 2;                         // groups of 4 edges
    int d[4];
    if (g_is64) {
        const longlong2* p = (const longlong2*)dstv;
        for (int g = tid; g < P; g += S) {
            longlong2 a = __ldcs(p + 2 * g);
            longlong2 b = __ldcs(p + 2 * g + 1);
            d[0] = (int)a.x; d[1] = (int)a.y; d[2] = (int)b.x; d[3] = (int)b.y;
#pragma unroll
            for (int j = 0; j < 4; j++) atomicAdd(&g_deg[d[j]], 1);
        }
        // tail
        if (tid < (E & 3)) {
            int e = (P << 2) + tid;
            atomicAdd(&g_deg[(int)__ldcs((const long long*)dstv + e)], 1);
        }
    } else {
        const int4* p = (const int4*)dstv;
        for (int g = tid; g < P; g += S) {
            int4 a = __ldcs(p + g);
            atomicAdd(&g_deg[a.x], 1); atomicAdd(&g_deg[a.y], 1);
            atomicAdd(&g_deg[a.z], 1); atomicAdd(&g_deg[a.w], 1);
        }
        if (tid < (E & 3)) {
            int e = (P << 2) + tid;
            atomicAdd(&g_deg[__ldcs((const int*)dstv + e)], 1);
        }
    }
}

// --- per-node: 2 nodes/thread, 8 loads in flight ---
__global__ void k_node(const float* __restrict__ x, int N, int H) {
    __shared__ float sM0[32], sM1[32], sM2[32];
    if (threadIdx.x < 32) {
        sM0[threadIdx.x] = g_M0[threadIdx.x];
        sM1[threadIdx.x] = g_M1[threadIdx.x];
        sM2[threadIdx.x] = g_M2[threadIdx.x];
    }
    __syncthreads();
    int t = blockIdx.x * blockDim.x + threadIdx.x;
    if (t >= H) return;
    int i0 = t, i1 = t + H;
    bool v1 = (i1 < N);
    // issue all loads first
    float4 xa[4], xb[4];
    const float4* r0 = (const float4*)(x + (size_t)i0 * IN_FEATS);
    const float4* r1 = (const float4*)(x + (size_t)(v1 ? i1 : i0) * IN_FEATS);
#pragma unroll
    for (int q = 0; q < 4; q++) xa[q] = __ldg(r0 + q);
#pragma unroll
    for (int q = 0; q < 4; q++) xb[q] = __ldg(r1 + q);
    int d0 = g_deg[i0];
    int d1 = g_deg[v1 ? i1 : i0];

#pragma unroll
    for (int half = 0; half < 2; half++) {
        int i = half ? i1 : i0;
        if (half && !v1) break;
        float4* xr = half ? xb : xa;
        float nrm = rsqrtf((float)max(half ? d1 : d0, 1));
        g_norm[i] = nrm;
        float u0 = 0.f, u1 = 0.f, u2 = 0.f, u3 = 0.f, a0 = 0.f, a1 = 0.f;
#pragma unroll
        for (int q = 0; q < 4; q++) {
            float vals[4] = {xr[q].x, xr[q].y, xr[q].z, xr[q].w};
#pragma unroll
            for (int tt = 0; tt < 4; tt++) {
                int j = q * 4 + tt;
                float xj = vals[tt];
                a0 += xj * sM0[2 * j];  a1 += xj * sM0[2 * j + 1];
                u0 += xj * sM1[2 * j];  u1 += xj * sM1[2 * j + 1];
                u2 += xj * sM2[2 * j];  u3 += xj * sM2[2 * j + 1];
            }
        }
        g_Us[i] = make_float4(u0 * nrm, u1 * nrm, u2 * nrm, u3 * nrm);
        g_XA[i] = make_float2(a0, a1);
    }
}

__device__ __forceinline__ int ld_idx(const void* p, int e, int is64) {
    return is64 ? (int)__ldcs((const long long*)p + e)
                : __ldcs((const int*)p + e);
}

// --- prop1: exact-grid variant (E divisible by TB*UNROLL) ---
template <bool EXACT>
__global__ void k_prop1(const void* __restrict__ srcv,
                        const void* __restrict__ dstv, int E) {
    int tid = blockIdx.x * blockDim.x + threadIdx.x;
    int S = gridDim.x * blockDim.x;
    int is64 = g_is64;
    int s[UNROLL], d[UNROLL]; bool v[UNROLL];
    float4 u[UNROLL];
#pragma unroll
    for (int j = 0; j < UNROLL; j++) {
        int e = tid + j * S;
        v[j] = EXACT || (e < E);
        int ee = v[j] ? e : 0;
        s[j] = ld_idx(srcv, ee, is64);
        d[j] = ld_idx(dstv, ee, is64);
    }
#pragma unroll
    for (int j = 0; j < UNROLL; j++)
        u[j] = __ldg(&g_Us[s[j]]);
#pragma unroll
    for (int j = 0; j < UNROLL; j++)
        if (v[j]) atomicAdd(&g_Vacc[d[j]], u[j]);
}

// --- finalize pass 1: Zs = norm²·(M2 part) ---
__global__ void k_fin1(int N) {
    int i = blockIdx.x * blockDim.x + threadIdx.x;
    if (i >= N) return;
    float nrm = g_norm[i];
    float4 vv = g_Vacc[i];
    float n2 = nrm * nrm;
    g_Zs[i] = make_float2(vv.z * n2, vv.w * n2);
}

// --- prop2 ---
template <bool EXACT>
__global__ void k_prop2(const void* __restrict__ srcv,
                        const void* __restrict__ dstv, int E) {
    int tid = blockIdx.x * blockDim.x + threadIdx.x;
    int S = gridDim.x * blockDim.x;
    int is64 = g_is64;
    int s[UNROLL], d[UNROLL]; bool v[UNROLL];
    float2 z[UNROLL];
#pragma unroll
    for (int j = 0; j < UNROLL; j++) {
        int e = tid + j * S;
        v[j] = EXACT || (e < E);
        int ee = v[j] ? e : 0;
        s[j] = ld_idx(srcv, ee, is64);
        d[j] = ld_idx(dstv, ee, is64);
    }
#pragma unroll
    for (int j = 0; j < UNROLL; j++)
        z[j] = __ldg(&g_Zs[s[j]]);
#pragma unroll
    for (int j = 0; j < UNROLL; j++)
        if (v[j]) atomicAdd(&g_Tacc[d[j]], z[j]);
}

// --- epilogue: h = relu(XA + nrm·Vacc.xy + nrm·Tacc) ---
__global__ void k_out(float2* __restrict__ out, int N) {
    int i = blockIdx.x * blockDim.x + threadIdx.x;
    if (i >= N) return;
    float nrm = g_norm[i];
    float4 vv = g_Vacc[i];
    float2 t = g_Tacc[i], a = g_XA[i];
    out[i] = make_float2(fmaxf(a.x + (vv.x + t.x) * nrm, 0.0f),
                         fmaxf(a.y + (vv.y + t.y) * nrm, 0.0f));
}

extern "C" void kernel_launch(void* const* d_in, const int* in_sizes, int n_in,
                              void* d_out, int out_size) {
    const float* in_feat = (const float*)d_in[0];
    const float* W       = (const float*)d_in[1];
    const void*  src     = d_in[2];
    const void*  dst     = d_in[3];
    const float* lam     = (const float*)d_in[4];

    int N = in_sizes[0] / IN_FEATS;
    int E = in_sizes[2];
    const int TB = 256;
    int nb  = (N + TB - 1) / TB;
    int H   = (N + 1) / 2;
    int hb  = (H + TB - 1) / TB;
    int eb4 = (E + TB * UNROLL - 1) / (TB * UNROLL);
    int dgb = min(3000, (E / 4 + TB - 1) / TB);
    bool exact = (E % (TB * UNROLL)) == 0;

    k_init<<<nb, TB>>>(W, lam, (const unsigned*)src, E, N);
    k_deg<<<dgb, TB>>>(dst, E);
    k_node<<<hb, TB>>>(in_feat, N, H);
    if (exact) k_prop1<true><<<eb4, TB>>>(src, dst, E);
    else       k_prop1<false><<<eb4, TB>>>(src, dst, E);
    k_fin1<<<nb, TB>>>(N);
    if (exact) k_prop2<true><<<eb4, TB>>>(src, dst, E);
    else       k_prop2<false><<<eb4, TB>>>(src, dst, E);
    k_out<<<nb, TB>>>((float2*)d_out, N);
}